// round 15
// baseline (speedup 1.0000x reference)
#include <cuda_runtime.h>
#include <cuda_bf16.h>
#include <math.h>
#include <stdint.h>

typedef __nv_bfloat16 bf16;

// Problem constants
#define B_   4
#define E_   32
#define D_   1024
#define NH_  16
#define NP_  4
#define LQ_  1024          // E*E
#define DH_  64            // D/NH

// ---------------------------------------------------------------------------
// Scratch (static device globals; allocation APIs are forbidden)
// ---------------------------------------------------------------------------
__device__ bf16  g_fn    [B_ * 4 * LQ_ * D_];   // 32 MB  LN(concat srcs), bf16
__device__ bf16  g_qn    [B_ * LQ_ * D_];       //  8 MB  LN(src3), bf16
__device__ bf16  g_val   [B_ * 4 * LQ_ * D_];   // 32 MB  CA value (bf16)
__device__ float g_offaw [B_ * LQ_ * 768];      // 12 MB  CA off(512)+aw(256, raw logits)
__device__ bf16  g_samp  [B_ * LQ_ * D_];       //  8 MB  CA sampled, bf16
__device__ float g_attn  [B_ * LQ_ * D_];       // 16 MB
__device__ bf16  g_attn1 [B_ * LQ_ * D_];       //  8 MB  LN(attn), bf16
__device__ bf16  g_val2  [B_ * LQ_ * D_];       //  8 MB  SA value (bf16)
__device__ float g_offaw2[B_ * LQ_ * 192];      //  3 MB  SA off(128)+aw(64, raw logits)
__device__ bf16  g_samp2 [B_ * LQ_ * D_];       //  8 MB  bf16
__device__ bf16  g_wrb   [5177344];             // 10.4 MB bf16 weights

// Weight segment offsets (elements) inside g_wrb
#define WOFF_CAVW 0
#define WOFF_CAOW 1048576
#define WOFF_CAAW 1572864
#define WOFF_CAPW 1835008
#define WOFF_SAVW 2883584
#define WOFF_SAOW 3932160
#define WOFF_SAAW 4063232
#define WOFF_SAPW 4128768
#define WTOT      5177344

// ---------------------------------------------------------------------------
// Helpers
// ---------------------------------------------------------------------------
__device__ __forceinline__ uint32_t smem_u32(const void* p) {
    uint32_t a;
    asm("{ .reg .u64 t; cvta.to.shared.u64 t, %1; cvt.u32.u64 %0, t; }"
        : "=r"(a) : "l"(p));
    return a;
}
__device__ __forceinline__ void cp16(uint32_t s, const void* g) {
    asm volatile("cp.async.cg.shared.global [%0], [%1], 16;\n" :: "r"(s), "l"(g));
}
__device__ __forceinline__ void cp16p(uint32_t s, const void* g, uint32_t nbytes) {
    asm volatile("cp.async.cg.shared.global [%0], [%1], 16, %2;\n"
                 :: "r"(s), "l"(g), "r"(nbytes));
}
__device__ __forceinline__ void ldsm4(uint32_t* r, uint32_t a) {
    asm volatile("ldmatrix.sync.aligned.m8n8.x4.shared.b16 {%0,%1,%2,%3}, [%4];"
                 : "=r"(r[0]), "=r"(r[1]), "=r"(r[2]), "=r"(r[3]) : "r"(a));
}
__device__ __forceinline__ void mma_bf16(float* d, const uint32_t* a,
                                         uint32_t b0, uint32_t b1) {
    asm volatile(
        "mma.sync.aligned.m16n8k16.row.col.f32.bf16.bf16.f32 "
        "{%0,%1,%2,%3}, {%4,%5,%6,%7}, {%8,%9}, {%0,%1,%2,%3};"
        : "+f"(d[0]), "+f"(d[1]), "+f"(d[2]), "+f"(d[3])
        : "r"(a[0]), "r"(a[1]), "r"(a[2]), "r"(a[3]), "r"(b0), "r"(b1));
}
__device__ __forceinline__ uint32_t pack_bf16(float lo, float hi) {
    __nv_bfloat162 p = __floats2bfloat162_rn(lo, hi);
    return *reinterpret_cast<uint32_t*>(&p);
}

// ---------------------------------------------------------------------------
// BF16 tensor-core GEMM body (at legacy-HMMA issue floor per SM).
// Block 128xBNx32, 256 threads / 8 warps (warp tile 32 x BN/2), 4-stage
// cp.async, wait_group 2. BN=128 for well-packed big launches, BN=64 for
// small launches (finer CTA granularity -> less wave quantization).
// mode: 0 = fp32 C + bias, 1 = bf16 C + bias,
//       2 = FINAL: C(out) = fs3 + g1*(fat + g2*(acc + bias))   [fp32, N=1024]
// ---------------------------------------------------------------------------
#define RSTR 80              // bytes per smem row
#define NSTAGE 4

struct GDesc {
    const bf16* A; const bf16* W;
    const float* b1; const float* b2;
    int split; void* C; int N; int gx; int mode;
    const float* fs3; const float* fat; const float* fg1; const float* fg2;
};

template<int BN>
__device__ __forceinline__ void gemm_body(const GDesc d, int bx, int by)
{
    constexpr int STGA = 128 * RSTR;        // A stage bytes
    constexpr int STGBB = BN * RSTR;        // B stage bytes
    constexpr int NT = BN / 16;             // 8-wide n-subtiles per warp
    constexpr int NB = BN / 32;             // ldsm4 tiles per warp per ks

    extern __shared__ char smraw[];
    uint32_t abase = smem_u32(smraw);
    uint32_t bbase = abase + NSTAGE * STGA;

    const int K = 1024, NIT = 32;
    int tid = threadIdx.x, wid = tid >> 5, lane = tid & 31;
    int wm = wid & 3, wn = wid >> 2;
    int bm = by * 128, bn = bx * BN;
    int N = d.N;

    float acc[2][NT][4];
    #pragma unroll
    for (int mt = 0; mt < 2; mt++)
        #pragma unroll
        for (int nt = 0; nt < NT; nt++)
            #pragma unroll
            for (int i = 0; i < 4; i++) acc[mt][nt][i] = 0.f;

    int rowC = tid >> 2, jc = tid & 3;

    auto load_stage = [&](int s, int it) {
        int k0 = it * 32;
        #pragma unroll
        for (int i = 0; i < 2; ++i) {            // A: 128 rows
            int row = rowC + i * 64;
            cp16(abase + s * STGA + row * RSTR + jc * 16,
                 d.A + (size_t)(bm + row) * K + k0 + jc * 8);
        }
        #pragma unroll
        for (int i = 0; i < BN / 64; ++i) {      // B: BN rows
            int row = rowC + i * 64;
            int srow = bn + row;
            const bf16* src = d.W + (size_t)(srow < N ? srow : 0) * K + k0 + jc * 8;
            cp16p(bbase + s * STGBB + row * RSTR + jc * 16,
                  src, srow < N ? 16u : 0u);
        }
        asm volatile("cp.async.commit_group;" ::: "memory");
    };

    int rA = lane & 15, hA = lane >> 4;
    uint32_t aAddr = abase + (uint32_t)(wm * 32 + rA) * RSTR + hA * 16;
    int rB = (lane & 7) | ((lane >> 4) << 3);
    int hB = (lane >> 3) & 1;
    uint32_t bAddr = bbase + (uint32_t)(wn * (BN / 2) + rB) * RSTR + hB * 16;

    load_stage(0, 0);
    load_stage(1, 1);
    load_stage(2, 2);

    int s = 0, pf = 3;
    for (int it = 0; it < NIT; ++it) {
        asm volatile("cp.async.wait_group 2;" ::: "memory");
        __syncthreads();
        if (it + 3 < NIT) {
            load_stage(pf, it + 3);
            pf = (pf == NSTAGE - 1) ? 0 : pf + 1;
        }

        uint32_t ao = aAddr + s * STGA;
        uint32_t bo = bAddr + s * STGBB;
        #pragma unroll
        for (int ks = 0; ks < 2; ks++) {
            uint32_t af[2][4];
            #pragma unroll
            for (int mt = 0; mt < 2; mt++)
                ldsm4(af[mt], ao + mt * (16 * RSTR) + ks * 32);
            #pragma unroll
            for (int nb = 0; nb < NB; nb++) {
                uint32_t bb4[4];
                ldsm4(bb4, bo + nb * (16 * RSTR) + ks * 32);
                #pragma unroll
                for (int mt = 0; mt < 2; mt++) {
                    mma_bf16(acc[mt][2 * nb],     af[mt], bb4[0], bb4[1]);
                    mma_bf16(acc[mt][2 * nb + 1], af[mt], bb4[2], bb4[3]);
                }
            }
        }
        s = (s == NSTAGE - 1) ? 0 : s + 1;
    }

    // Epilogue (split-bias; mode-selected output transform)
    int gq = lane >> 2, c = lane & 3;
    #pragma unroll
    for (int mt = 0; mt < 2; mt++) {
        int r0 = bm + wm * 32 + mt * 16 + gq;
        #pragma unroll
        for (int nt = 0; nt < NT; nt++) {
            int colb = bn + wn * (BN / 2) + nt * 8;
            if (colb < N) {
                int cg = colb + 2 * c;
                const float* bp = (colb < d.split) ? (d.b1 + cg) : (d.b2 + cg - d.split);
                float2 bv = *(const float2*)bp;
                float v00 = acc[mt][nt][0] + bv.x, v01 = acc[mt][nt][1] + bv.y;
                float v10 = acc[mt][nt][2] + bv.x, v11 = acc[mt][nt][3] + bv.y;
                if (d.mode == 1) {
                    *(uint32_t*)((bf16*)d.C + (size_t)r0 * N + cg) = pack_bf16(v00, v01);
                    *(uint32_t*)((bf16*)d.C + (size_t)(r0 + 8) * N + cg) = pack_bf16(v10, v11);
                } else if (d.mode == 0) {
                    *(float2*)((float*)d.C + (size_t)r0 * N + cg) = make_float2(v00, v01);
                    *(float2*)((float*)d.C + (size_t)(r0 + 8) * N + cg) = make_float2(v10, v11);
                } else {
                    float2 G1 = *(const float2*)(d.fg1 + cg);
                    float2 G2 = *(const float2*)(d.fg2 + cg);
                    float2 s0v = *(const float2*)(d.fs3 + (size_t)r0 * N + cg);
                    float2 a0v = *(const float2*)(d.fat + (size_t)r0 * N + cg);
                    float2 o0 = { s0v.x + G1.x * (a0v.x + G2.x * v00),
                                  s0v.y + G1.y * (a0v.y + G2.y * v01) };
                    *(float2*)((float*)d.C + (size_t)r0 * N + cg) = o0;
                    float2 s1v = *(const float2*)(d.fs3 + (size_t)(r0 + 8) * N + cg);
                    float2 a1v = *(const float2*)(d.fat + (size_t)(r0 + 8) * N + cg);
                    float2 o1 = { s1v.x + G1.x * (a1v.x + G2.x * v10),
                                  s1v.y + G1.y * (a1v.y + G2.y * v11) };
                    *(float2*)((float*)d.C + (size_t)(r0 + 8) * N + cg) = o1;
                }
            }
        }
    }
}

template<int BN>
__global__ void __launch_bounds__(256, 2) gemm_dual(GDesc d0, GDesc d1, int n0)
{
    int cta = blockIdx.x;
    if (cta < n0) {
        gemm_body<BN>(d0, cta % d0.gx, cta / d0.gx);
    } else {
        int idx = cta - n0;
        gemm_body<BN>(d1, idx % d1.gx, idx / d1.gx);
    }
}

// ---------------------------------------------------------------------------
// Warp-per-row LayerNorm: 8 warps/block = 8 rows/block, pure shfl reduction.
// fp32 in -> bf16 out.
// ---------------------------------------------------------------------------
__global__ void __launch_bounds__(256) ln_kernel(
    const float* __restrict__ in, const float* __restrict__ g,
    const float* __restrict__ b, bf16* __restrict__ out)
{
    int w = threadIdx.x >> 5, lane = threadIdx.x & 31;
    int r = blockIdx.x * 8 + w;
    const float4* x4 = (const float4*)(in + (size_t)r * D_);

    float4 v[8];
    float s = 0.f, ss = 0.f;
    #pragma unroll
    for (int i = 0; i < 8; i++) {
        v[i] = x4[lane + 32 * i];
        s  += v[i].x + v[i].y + v[i].z + v[i].w;
        ss += v[i].x * v[i].x + v[i].y * v[i].y + v[i].z * v[i].z + v[i].w * v[i].w;
    }
    #pragma unroll
    for (int o = 16; o; o >>= 1) {
        s  += __shfl_xor_sync(0xFFFFFFFFu, s,  o);
        ss += __shfl_xor_sync(0xFFFFFFFFu, ss, o);
    }
    float mean = s * (1.0f / D_);
    float var  = ss * (1.0f / D_) - mean * mean;
    float inv  = rsqrtf(var + 1e-6f);

    uint2* orow = (uint2*)(out + (size_t)r * D_);
    #pragma unroll
    for (int i = 0; i < 8; i++) {
        float4 gg = ((const float4*)g)[lane + 32 * i];
        float4 bb = ((const float4*)b)[lane + 32 * i];
        uint2 u;
        u.x = pack_bf16((v[i].x - mean) * inv * gg.x + bb.x,
                        (v[i].y - mean) * inv * gg.y + bb.y);
        u.y = pack_bf16((v[i].z - mean) * inv * gg.z + bb.z,
                        (v[i].w - mean) * inv * gg.w + bb.w);
        orow[lane + 32 * i] = u;
    }
}

// Warp-per-row fused feat-LN: 4 srcs -> concat layout, bf16. grid = 2048.
__global__ void __launch_bounds__(256) ln_feat_kernel(
    const float* __restrict__ s0, const float* __restrict__ s1,
    const float* __restrict__ s2, const float* __restrict__ s3,
    const float* __restrict__ g, const float* __restrict__ b,
    bf16* __restrict__ out)
{
    int w = threadIdx.x >> 5, lane = threadIdx.x & 31;
    int row = blockIdx.x * 8 + w;            // 0..16383
    int l = row >> 12;
    int r = row & 4095;
    const float* in = (l == 0) ? s0 : (l == 1) ? s1 : (l == 2) ? s2 : s3;
    int bb = r >> 10, rr = r & 1023;
    const float4* x4 = (const float4*)(in + (size_t)r * D_);
    uint2* orow = (uint2*)(out + ((size_t)bb * 4096 + l * 1024 + rr) * D_);

    float4 v[8];
    float s = 0.f, ss = 0.f;
    #pragma unroll
    for (int i = 0; i < 8; i++) {
        v[i] = x4[lane + 32 * i];
        s  += v[i].x + v[i].y + v[i].z + v[i].w;
        ss += v[i].x * v[i].x + v[i].y * v[i].y + v[i].z * v[i].z + v[i].w * v[i].w;
    }
    #pragma unroll
    for (int o = 16; o; o >>= 1) {
        s  += __shfl_xor_sync(0xFFFFFFFFu, s,  o);
        ss += __shfl_xor_sync(0xFFFFFFFFu, ss, o);
    }
    float mean = s * (1.0f / D_);
    float var  = ss * (1.0f / D_) - mean * mean;
    float inv  = rsqrtf(var + 1e-6f);

    #pragma unroll
    for (int i = 0; i < 8; i++) {
        float4 gg = ((const float4*)g)[lane + 32 * i];
        float4 bv = ((const float4*)b)[lane + 32 * i];
        uint2 u;
        u.x = pack_bf16((v[i].x - mean) * inv * gg.x + bv.x,
                        (v[i].y - mean) * inv * gg.y + bv.y);
        u.y = pack_bf16((v[i].z - mean) * inv * gg.z + bv.z,
                        (v[i].w - mean) * inv * gg.w + bv.w);
        orow[lane + 32 * i] = u;
    }
}

// ---------------------------------------------------------------------------
// Convert all 8 weight matrices to bf16 into g_wrb (single launch).
// ---------------------------------------------------------------------------
struct WPtrs { const float4 *p0,*p1,*p2,*p3,*p4,*p5,*p6,*p7; };

__global__ void round_weights(WPtrs w, bf16* __restrict__ dst)
{
    int i = blockIdx.x * blockDim.x + threadIdx.x;   // float4 index
    if (i >= WTOT / 4) return;
    const float4* src; int base;
    if      (i < WOFF_CAOW/4) { src = w.p0; base = 0; }
    else if (i < WOFF_CAAW/4) { src = w.p1; base = WOFF_CAOW/4; }
    else if (i < WOFF_CAPW/4) { src = w.p2; base = WOFF_CAAW/4; }
    else if (i < WOFF_SAVW/4) { src = w.p3; base = WOFF_CAPW/4; }
    else if (i < WOFF_SAOW/4) { src = w.p4; base = WOFF_SAVW/4; }
    else if (i < WOFF_SAAW/4) { src = w.p5; base = WOFF_SAOW/4; }
    else if (i < WOFF_SAPW/4) { src = w.p6; base = WOFF_SAAW/4; }
    else                      { src = w.p7; base = WOFF_SAPW/4; }
    float4 v = src[i - base];
    uint2 u;
    u.x = pack_bf16(v.x, v.y);
    u.y = pack_bf16(v.z, v.w);
    ((uint2*)dst)[i] = u;
}

// ---------------------------------------------------------------------------
// Deformable sampling with FUSED softmax over raw logits (per lane, from
// L1-broadcast loads). 1 block per (b,q), 16 warps = heads; value bf16.
// ---------------------------------------------------------------------------
template<int NL>
__global__ void __launch_bounds__(512) deform_sample(
    const bf16* __restrict__ value, const float* __restrict__ comb,
    int rstride, int aoff, bf16* __restrict__ out)
{
    constexpr int P = NL * NP_;
    int bq = blockIdx.x;
    int b = bq >> 10, q = bq & 1023;
    int h = threadIdx.x >> 5, lane = threadIdx.x & 31;

    float rx = ((q & 31) + 0.5f) * 0.03125f;
    float ry = ((q >> 5) + 0.5f) * 0.03125f;

    const float* offp = comb + (size_t)bq * rstride + h * (P * 2);
    const float* awp  = comb + (size_t)bq * rstride + aoff + h * P;
    const bf16* vbase = value + (size_t)b * (NL * 1024) * D_ + h * DH_;

    // Fused softmax over P raw logits
    float wsm[P];
    float m = -1e30f;
    #pragma unroll
    for (int s = 0; s < P; s++) { wsm[s] = awp[s]; m = fmaxf(m, wsm[s]); }
    float sum = 0.f;
    #pragma unroll
    for (int s = 0; s < P; s++) { wsm[s] = __expf(wsm[s] - m); sum += wsm[s]; }
    float isum = 1.0f / sum;

    float2 acc = make_float2(0.f, 0.f);

    #pragma unroll
    for (int l = 0; l < NL; l++) {
        #pragma unroll
        for (int p = 0; p < NP_; p++) {
            int s = l * NP_ + p;
            float ox = offp[s * 2 + 0];
            float oy = offp[s * 2 + 1];
            float a  = wsm[s] * isum;
            float x = (rx + ox * 0.03125f) * 32.0f - 0.5f;
            float y = (ry + oy * 0.03125f) * 32.0f - 0.5f;
            float x0f = floorf(x), y0f = floorf(y);
            float wx1 = x - x0f, wy1 = y - y0f;
            int x0 = (int)x0f, y0 = (int)y0f;
            #pragma unroll
            for (int dy = 0; dy < 2; dy++) {
                int yi = y0 + dy;
                if ((unsigned)yi >= 32u) continue;
                float wy = dy ? wy1 : (1.0f - wy1);
                #pragma unroll
                for (int dx = 0; dx < 2; dx++) {
                    int xi = x0 + dx;
                    if ((unsigned)xi >= 32u) continue;
                    float w = (dx ? wx1 : (1.0f - wx1)) * wy * a;
                    const uint32_t* vp = (const uint32_t*)(vbase +
                        ((size_t)l * 1024 + yi * 32 + xi) * D_);
                    uint32_t pv = vp[lane];
                    float2 v = __bfloat1622float2(*reinterpret_cast<__nv_bfloat162*>(&pv));
                    acc.x += v.x * w;
                    acc.y += v.y * w;
                }
            }
        }
    }
    uint32_t pv = pack_bf16(acc.x, acc.y);
    ((uint32_t*)(out + (size_t)bq * D_ + h * DH_))[lane] = pv;
}

// ---------------------------------------------------------------------------
// Host launcher
// ---------------------------------------------------------------------------
extern "C" void kernel_launch(void* const* d_in, const int* in_sizes, int n_in,
                              void* d_out, int out_size)
{
    const float* src[4] = {(const float*)d_in[0], (const float*)d_in[1],
                           (const float*)d_in[2], (const float*)d_in[3]};
    const float* qn_g = (const float*)d_in[4];
    const float* qn_b = (const float*)d_in[5];
    const float* fn_g = (const float*)d_in[6];
    const float* fn_b = (const float*)d_in[7];
    const float* n1_g = (const float*)d_in[8];
    const float* n1_b = (const float*)d_in[9];
    const float* gamma1 = (const float*)d_in[10];
    const float* gamma2 = (const float*)d_in[11];
    const float* ca_vb = (const float*)d_in[13];
    const float* ca_ob = (const float*)d_in[15];
    const float* ca_ab = (const float*)d_in[17];
    const float* ca_pb = (const float*)d_in[19];
    const float* sa_vb = (const float*)d_in[21];
    const float* sa_ob = (const float*)d_in[23];
    const float* sa_ab = (const float*)d_in[25];
    const float* sa_pb = (const float*)d_in[27];

    bf16 *fn, *qn, *val, *samp, *attn1, *val2, *samp2, *wr;
    float *offaw, *attn, *offaw2;
    cudaGetSymbolAddress((void**)&fn,     g_fn);
    cudaGetSymbolAddress((void**)&qn,     g_qn);
    cudaGetSymbolAddress((void**)&val,    g_val);
    cudaGetSymbolAddress((void**)&offaw,  g_offaw);
    cudaGetSymbolAddress((void**)&samp,   g_samp);
    cudaGetSymbolAddress((void**)&attn,   g_attn);
    cudaGetSymbolAddress((void**)&attn1,  g_attn1);
    cudaGetSymbolAddress((void**)&val2,   g_val2);
    cudaGetSymbolAddress((void**)&offaw2, g_offaw2);
    cudaGetSymbolAddress((void**)&samp2,  g_samp2);
    cudaGetSymbolAddress((void**)&wr,     g_wrb);

    const int ROWS = B_ * LQ_;                            // 4096
    const int SMEM128 = NSTAGE * (128 + 128) * RSTR;      // 81920
    const int SMEM64  = NSTAGE * (128 + 64) * RSTR;       // 61440

    cudaFuncSetAttribute(gemm_dual<128>, cudaFuncAttributeMaxDynamicSharedMemorySize, SMEM128);
    cudaFuncSetAttribute(gemm_dual<64>,  cudaFuncAttributeMaxDynamicSharedMemorySize, SMEM64);

    WPtrs wp = { (const float4*)d_in[12], (const float4*)d_in[14],
                 (const float4*)d_in[16], (const float4*)d_in[18],
                 (const float4*)d_in[20], (const float4*)d_in[22],
                 (const float4*)d_in[24], (const float4*)d_in[26] };

    const float* Z = nullptr;
    // Descriptors {A, W, b1, b2, split, C, N, gx, mode, fs3, fat, fg1, fg2}
    GDesc dCAoffaw = { qn,    wr + WOFF_CAOW, ca_ob, ca_ab, 512,  offaw,  768,  6,  0, Z, Z, Z, Z };
    GDesc dCAval   = { fn,    wr + WOFF_CAVW, ca_vb, ca_vb, 1024, val,    1024, 8,  1, Z, Z, Z, Z };
    GDesc dCAproj  = { samp,  wr + WOFF_CAPW, ca_pb, ca_pb, 1024, attn,   1024, 16, 0, Z, Z, Z, Z };
    GDesc dSAval   = { attn1, wr + WOFF_SAVW, sa_vb, sa_vb, 1024, val2,   1024, 16, 1, Z, Z, Z, Z };
    GDesc dSAoffaw = { attn1, wr + WOFF_SAOW, sa_ob, sa_ab, 128,  offaw2, 192,  3,  0, Z, Z, Z, Z };
    GDesc dSAproj  = { samp2, wr + WOFF_SAPW, sa_pb, sa_pb, 1024, d_out,  1024, 16, 2,
                       src[3], attn, gamma1, gamma2 };

    // 1-3) LayerNorms (warp-per-row) + weight conversion
    ln_feat_kernel<<<4 * ROWS / 8, 256>>>(src[0], src[1], src[2], src[3], fn_g, fn_b, fn);
    ln_kernel<<<ROWS / 8, 256>>>(src[3], qn_g, qn_b, qn);
    round_weights<<<(WTOT / 4 + 255) / 256, 256>>>(wp, wr);
    // 4) Combined CA GEMMs (BN=128, well-packed): off+aw (192) || value (1024)
    gemm_dual<128><<<192 + 1024, 256, SMEM128>>>(dCAoffaw, dCAval, 192);
    // 5) CA sampler (softmax fused)
    deform_sample<4><<<ROWS, 512>>>(val, offaw, 768, 512, samp);
    // 6) CA projection (BN=64: 512 CTAs, fine-grained)
    gemm_dual<64><<<512, 256, SMEM64>>>(dCAproj, dCAproj, 512);
    // 7) LN(attn) -> attn1
    ln_kernel<<<ROWS / 8, 256>>>(attn, n1_g, n1_b, attn1);
    // 8) SA value || SA off+aw (BN=64: 512 + 96 CTAs)
    gemm_dual<64><<<512 + 96, 256, SMEM64>>>(dSAval, dSAoffaw, 512);
    // 9) SA sampler
    deform_sample<1><<<ROWS, 512>>>(val2, offaw2, 192, 128, samp2);
    // 10) SA projection with FINAL fused epilogue -> d_out (BN=64)
    gemm_dual<64><<<512, 256, SMEM64>>>(dSAproj, dSAproj, 512);
}

// round 16
// speedup vs baseline: 1.2031x; 1.2031x over previous
#include <cuda_runtime.h>
#include <cuda_bf16.h>
#include <math.h>
#include <stdint.h>

typedef __nv_bfloat16 bf16;

// Problem constants
#define B_   4
#define E_   32
#define D_   1024
#define NH_  16
#define NP_  4
#define LQ_  1024          // E*E
#define DH_  64            // D/NH

// ---------------------------------------------------------------------------
// Scratch (static device globals; allocation APIs are forbidden)
// ---------------------------------------------------------------------------
__device__ bf16  g_fn    [B_ * 4 * LQ_ * D_];   // 32 MB  LN(concat srcs), bf16
__device__ bf16  g_qn    [B_ * LQ_ * D_];       //  8 MB  LN(src3), bf16
__device__ bf16  g_val   [B_ * 4 * LQ_ * D_];   // 32 MB  CA value (bf16)
__device__ float g_offaw [B_ * LQ_ * 768];      // 12 MB  CA off(512)+aw(256, raw logits)
__device__ bf16  g_samp  [B_ * LQ_ * D_];       //  8 MB  CA sampled, bf16
__device__ float g_attn  [B_ * LQ_ * D_];       // 16 MB
__device__ bf16  g_attn1 [B_ * LQ_ * D_];       //  8 MB  LN(attn), bf16
__device__ bf16  g_val2  [B_ * LQ_ * D_];       //  8 MB  SA value (bf16)
__device__ float g_offaw2[B_ * LQ_ * 192];      //  3 MB  SA off(128)+aw(64, raw logits)
__device__ bf16  g_samp2 [B_ * LQ_ * D_];       //  8 MB  bf16
__device__ bf16  g_wrb   [5177344];             // 10.4 MB bf16 weights

// Weight segment offsets (elements) inside g_wrb
#define WOFF_CAVW 0
#define WOFF_CAOW 1048576
#define WOFF_CAAW 1572864
#define WOFF_CAPW 1835008
#define WOFF_SAVW 2883584
#define WOFF_SAOW 3932160
#define WOFF_SAAW 4063232
#define WOFF_SAPW 4128768
#define WTOT      5177344

// ---------------------------------------------------------------------------
// Helpers
// ---------------------------------------------------------------------------
__device__ __forceinline__ uint32_t smem_u32(const void* p) {
    uint32_t a;
    asm("{ .reg .u64 t; cvta.to.shared.u64 t, %1; cvt.u32.u64 %0, t; }"
        : "=r"(a) : "l"(p));
    return a;
}
__device__ __forceinline__ void cp16(uint32_t s, const void* g) {
    asm volatile("cp.async.cg.shared.global [%0], [%1], 16;\n" :: "r"(s), "l"(g));
}
__device__ __forceinline__ void cp16p(uint32_t s, const void* g, uint32_t nbytes) {
    asm volatile("cp.async.cg.shared.global [%0], [%1], 16, %2;\n"
                 :: "r"(s), "l"(g), "r"(nbytes));
}
__device__ __forceinline__ void ldsm4(uint32_t* r, uint32_t a) {
    asm volatile("ldmatrix.sync.aligned.m8n8.x4.shared.b16 {%0,%1,%2,%3}, [%4];"
                 : "=r"(r[0]), "=r"(r[1]), "=r"(r[2]), "=r"(r[3]) : "r"(a));
}
__device__ __forceinline__ void mma_bf16(float* d, const uint32_t* a,
                                         uint32_t b0, uint32_t b1) {
    asm volatile(
        "mma.sync.aligned.m16n8k16.row.col.f32.bf16.bf16.f32 "
        "{%0,%1,%2,%3}, {%4,%5,%6,%7}, {%8,%9}, {%0,%1,%2,%3};"
        : "+f"(d[0]), "+f"(d[1]), "+f"(d[2]), "+f"(d[3])
        : "r"(a[0]), "r"(a[1]), "r"(a[2]), "r"(a[3]), "r"(b0), "r"(b1));
}
__device__ __forceinline__ uint32_t pack_bf16(float lo, float hi) {
    __nv_bfloat162 p = __floats2bfloat162_rn(lo, hi);
    return *reinterpret_cast<uint32_t*>(&p);
}

// ---------------------------------------------------------------------------
// BF16 tensor-core GEMM body (at legacy-HMMA issue floor per SM; BN=128 only
// — BN=64 measured worse: load phase doesn't shrink with the tile).
// Block 128x128x32, 256 threads / 8 warps (warp 32x64), 4-stage cp.async,
// wait_group 2. gemm_dual packs two independent descriptors in ONE launch.
// mode: 0 = fp32 C + bias, 1 = bf16 C + bias,
//       2 = FINAL: C(out) = fs3 + g1*(fat + g2*(acc + bias))   [fp32, N=1024]
// ---------------------------------------------------------------------------
#define RSTR 80              // bytes per smem row
#define STGB (128 * RSTR)    // bytes per matrix per stage (10240)
#define NSTAGE 4

struct GDesc {
    const bf16* A; const bf16* W;
    const float* b1; const float* b2;
    int split; void* C; int N; int gx; int mode;
    const float* fs3; const float* fat; const float* fg1; const float* fg2;
};

__device__ __forceinline__ void gemm_body(const GDesc d, int bx, int by)
{
    extern __shared__ char smraw[];
    uint32_t abase = smem_u32(smraw);
    uint32_t bbase = abase + NSTAGE * STGB;

    const int K = 1024, NIT = 32;
    int tid = threadIdx.x, wid = tid >> 5, lane = tid & 31;
    int wm = wid & 3, wn = wid >> 2;
    int bm = by * 128, bn = bx * 128;
    int N = d.N;

    float acc[2][8][4];
    #pragma unroll
    for (int mt = 0; mt < 2; mt++)
        #pragma unroll
        for (int nt = 0; nt < 8; nt++)
            #pragma unroll
            for (int i = 0; i < 4; i++) acc[mt][nt][i] = 0.f;

    int rowC = tid >> 2, jc = tid & 3;

    auto load_stage = [&](int s, int it) {
        int k0 = it * 32;
        #pragma unroll
        for (int i = 0; i < 2; ++i) {
            int row = rowC + i * 64;
            cp16(abase + s * STGB + row * RSTR + jc * 16,
                 d.A + (size_t)(bm + row) * K + k0 + jc * 8);
            int srow = bn + row;
            const bf16* src = d.W + (size_t)(srow < N ? srow : 0) * K + k0 + jc * 8;
            cp16p(bbase + s * STGB + row * RSTR + jc * 16,
                  src, srow < N ? 16u : 0u);
        }
        asm volatile("cp.async.commit_group;" ::: "memory");
    };

    int rA = lane & 15, hA = lane >> 4;
    uint32_t aAddr = abase + (uint32_t)(wm * 32 + rA) * RSTR + hA * 16;
    int rB = (lane & 7) | ((lane >> 4) << 3);
    int hB = (lane >> 3) & 1;
    uint32_t bAddr = bbase + (uint32_t)(wn * 64 + rB) * RSTR + hB * 16;

    load_stage(0, 0);
    load_stage(1, 1);
    load_stage(2, 2);

    int s = 0, pf = 3;
    for (int it = 0; it < NIT; ++it) {
        asm volatile("cp.async.wait_group 2;" ::: "memory");
        __syncthreads();
        if (it + 3 < NIT) {
            load_stage(pf, it + 3);
            pf = (pf == NSTAGE - 1) ? 0 : pf + 1;
        }

        uint32_t ao = aAddr + s * STGB;
        uint32_t bo = bAddr + s * STGB;
        #pragma unroll
        for (int ks = 0; ks < 2; ks++) {
            uint32_t af[2][4];
            #pragma unroll
            for (int mt = 0; mt < 2; mt++)
                ldsm4(af[mt], ao + mt * (16 * RSTR) + ks * 32);
            #pragma unroll
            for (int nb = 0; nb < 4; nb++) {
                uint32_t bb4[4];
                ldsm4(bb4, bo + nb * (16 * RSTR) + ks * 32);
                #pragma unroll
                for (int mt = 0; mt < 2; mt++) {
                    mma_bf16(acc[mt][2 * nb],     af[mt], bb4[0], bb4[1]);
                    mma_bf16(acc[mt][2 * nb + 1], af[mt], bb4[2], bb4[3]);
                }
            }
        }
        s = (s == NSTAGE - 1) ? 0 : s + 1;
    }

    // Epilogue (split-bias; mode-selected output transform)
    int gq = lane >> 2, c = lane & 3;
    #pragma unroll
    for (int mt = 0; mt < 2; mt++) {
        int r0 = bm + wm * 32 + mt * 16 + gq;
        #pragma unroll
        for (int nt = 0; nt < 8; nt++) {
            int colb = bn + wn * 64 + nt * 8;
            if (colb < N) {
                int cg = colb + 2 * c;
                const float* bp = (colb < d.split) ? (d.b1 + cg) : (d.b2 + cg - d.split);
                float2 bv = *(const float2*)bp;
                float v00 = acc[mt][nt][0] + bv.x, v01 = acc[mt][nt][1] + bv.y;
                float v10 = acc[mt][nt][2] + bv.x, v11 = acc[mt][nt][3] + bv.y;
                if (d.mode == 1) {
                    *(uint32_t*)((bf16*)d.C + (size_t)r0 * N + cg) = pack_bf16(v00, v01);
                    *(uint32_t*)((bf16*)d.C + (size_t)(r0 + 8) * N + cg) = pack_bf16(v10, v11);
                } else if (d.mode == 0) {
                    *(float2*)((float*)d.C + (size_t)r0 * N + cg) = make_float2(v00, v01);
                    *(float2*)((float*)d.C + (size_t)(r0 + 8) * N + cg) = make_float2(v10, v11);
                } else {
                    float2 G1 = *(const float2*)(d.fg1 + cg);
                    float2 G2 = *(const float2*)(d.fg2 + cg);
                    float2 s0v = *(const float2*)(d.fs3 + (size_t)r0 * N + cg);
                    float2 a0v = *(const float2*)(d.fat + (size_t)r0 * N + cg);
                    float2 o0 = { s0v.x + G1.x * (a0v.x + G2.x * v00),
                                  s0v.y + G1.y * (a0v.y + G2.y * v01) };
                    *(float2*)((float*)d.C + (size_t)r0 * N + cg) = o0;
                    float2 s1v = *(const float2*)(d.fs3 + (size_t)(r0 + 8) * N + cg);
                    float2 a1v = *(const float2*)(d.fat + (size_t)(r0 + 8) * N + cg);
                    float2 o1 = { s1v.x + G1.x * (a1v.x + G2.x * v10),
                                  s1v.y + G1.y * (a1v.y + G2.y * v11) };
                    *(float2*)((float*)d.C + (size_t)(r0 + 8) * N + cg) = o1;
                }
            }
        }
    }
}

__global__ void __launch_bounds__(256, 2) gemm_dual(GDesc d0, GDesc d1, int n0)
{
    int cta = blockIdx.x;
    if (cta < n0) {
        gemm_body(d0, cta % d0.gx, cta / d0.gx);
    } else {
        int idx = cta - n0;
        gemm_body(d1, idx % d1.gx, idx / d1.gx);
    }
}

// ---------------------------------------------------------------------------
// Warp-per-row LN body (pure shfl reduction). fp32 row -> bf16 row.
// ---------------------------------------------------------------------------
__device__ __forceinline__ void ln_row(
    const float4* __restrict__ x4, const float* __restrict__ g,
    const float* __restrict__ b, uint2* __restrict__ orow, int lane)
{
    float4 v[8];
    float s = 0.f, ss = 0.f;
    #pragma unroll
    for (int i = 0; i < 8; i++) {
        v[i] = x4[lane + 32 * i];
        s  += v[i].x + v[i].y + v[i].z + v[i].w;
        ss += v[i].x * v[i].x + v[i].y * v[i].y + v[i].z * v[i].z + v[i].w * v[i].w;
    }
    #pragma unroll
    for (int o = 16; o; o >>= 1) {
        s  += __shfl_xor_sync(0xFFFFFFFFu, s,  o);
        ss += __shfl_xor_sync(0xFFFFFFFFu, ss, o);
    }
    float mean = s * (1.0f / D_);
    float var  = ss * (1.0f / D_) - mean * mean;
    float inv  = rsqrtf(var + 1e-6f);

    #pragma unroll
    for (int i = 0; i < 8; i++) {
        float4 gg = ((const float4*)g)[lane + 32 * i];
        float4 bb = ((const float4*)b)[lane + 32 * i];
        uint2 u;
        u.x = pack_bf16((v[i].x - mean) * inv * gg.x + bb.x,
                        (v[i].y - mean) * inv * gg.y + bb.y);
        u.y = pack_bf16((v[i].z - mean) * inv * gg.z + bb.z,
                        (v[i].w - mean) * inv * gg.w + bb.w);
        orow[lane + 32 * i] = u;
    }
}

__global__ void __launch_bounds__(256) ln_kernel(
    const float* __restrict__ in, const float* __restrict__ g,
    const float* __restrict__ b, bf16* __restrict__ out)
{
    int w = threadIdx.x >> 5, lane = threadIdx.x & 31;
    int r = blockIdx.x * 8 + w;
    ln_row((const float4*)(in + (size_t)r * D_), g, b,
           (uint2*)(out + (size_t)r * D_), lane);
}

// ---------------------------------------------------------------------------
// Merged prologue: blocks [0,2048) feat-LN, [2048,2560) qn-LN,
// [2560, 2560+5056) weight bf16 conversion. All independent work.
// ---------------------------------------------------------------------------
struct PrepArgs {
    const float *s0, *s1, *s2, *s3;
    const float *fng, *fnb, *qng, *qnb;
    bf16 *fn, *qn, *wrb;
    const float4 *w0, *w1, *w2, *w3, *w4, *w5, *w6, *w7;
};

__global__ void __launch_bounds__(256) prep_kernel(PrepArgs a)
{
    int bid = blockIdx.x, tid = threadIdx.x;
    if (bid < 2560) {
        int w = tid >> 5, lane = tid & 31;
        if (bid < 2048) {
            int row = bid * 8 + w;             // 0..16383
            int l = row >> 12, r = row & 4095;
            const float* in = (l == 0) ? a.s0 : (l == 1) ? a.s1 : (l == 2) ? a.s2 : a.s3;
            int bb = r >> 10, rr = r & 1023;
            ln_row((const float4*)(in + (size_t)r * D_), a.fng, a.fnb,
                   (uint2*)(a.fn + ((size_t)bb * 4096 + l * 1024 + rr) * D_), lane);
        } else {
            int r = (bid - 2048) * 8 + w;      // 0..4095
            ln_row((const float4*)(a.s3 + (size_t)r * D_), a.qng, a.qnb,
                   (uint2*)(a.qn + (size_t)r * D_), lane);
        }
    } else {
        int i = (bid - 2560) * 256 + tid;      // float4 index
        if (i >= WTOT / 4) return;
        const float4* src; int base;
        if      (i < WOFF_CAOW/4) { src = a.w0; base = 0; }
        else if (i < WOFF_CAAW/4) { src = a.w1; base = WOFF_CAOW/4; }
        else if (i < WOFF_CAPW/4) { src = a.w2; base = WOFF_CAAW/4; }
        else if (i < WOFF_SAVW/4) { src = a.w3; base = WOFF_CAPW/4; }
        else if (i < WOFF_SAOW/4) { src = a.w4; base = WOFF_SAVW/4; }
        else if (i < WOFF_SAAW/4) { src = a.w5; base = WOFF_SAOW/4; }
        else if (i < WOFF_SAPW/4) { src = a.w6; base = WOFF_SAAW/4; }
        else                      { src = a.w7; base = WOFF_SAPW/4; }
        float4 v = src[i - base];
        uint2 u;
        u.x = pack_bf16(v.x, v.y);
        u.y = pack_bf16(v.z, v.w);
        ((uint2*)a.wrb)[i] = u;
    }
}

// ---------------------------------------------------------------------------
// Deformable sampling, de-redundified: lane j (mod P) computes sample j's
// softmax weight (1 expf + width-P butterfly), bilinear weights and row
// indices ONCE; (weight,index) pairs staged in smem; gather loop is
// branch-free LDS.64-broadcast + gather LDG + 2 FFMA per corner (invalid
// corner -> index 0, weight 0). 1 block per (b,q), 16 warps = heads.
// ---------------------------------------------------------------------------
template<int NL>
__global__ void __launch_bounds__(512) deform_sample(
    const bf16* __restrict__ value, const float* __restrict__ comb,
    int rstride, int aoff, bf16* __restrict__ out)
{
    constexpr int P = NL * NP_;
    __shared__ uint2 swc[16][P][4];

    int bq = blockIdx.x;
    int b = bq >> 10, q = bq & 1023;
    int h = threadIdx.x >> 5, lane = threadIdx.x & 31;

    const bf16* vbase = value + (size_t)b * (NL * 1024) * D_ + h * DH_;

    // ---- per-sample setup on lanes (duplicated mod P) ----
    int j = lane & (P - 1);
    const float* base = comb + (size_t)bq * rstride;
    float ox    = base[h * (P * 2) + 2 * j];
    float oy    = base[h * (P * 2) + 2 * j + 1];
    float logit = base[aoff + h * P + j];

    float m = logit;
    #pragma unroll
    for (int o = P / 2; o; o >>= 1)
        m = fmaxf(m, __shfl_xor_sync(0xFFFFFFFFu, m, o, P));
    float e = __expf(logit - m);
    float sum = e;
    #pragma unroll
    for (int o = P / 2; o; o >>= 1)
        sum += __shfl_xor_sync(0xFFFFFFFFu, sum, o, P);
    float aw = e / sum;

    float rx = ((q & 31) + 0.5f) * 0.03125f;
    float ry = ((q >> 5) + 0.5f) * 0.03125f;
    float x = (rx + ox * 0.03125f) * 32.0f - 0.5f;
    float y = (ry + oy * 0.03125f) * 32.0f - 0.5f;
    float x0f = floorf(x), y0f = floorf(y);
    float wx1 = x - x0f, wy1 = y - y0f;
    int x0 = (int)x0f, y0 = (int)y0f;
    int l = j >> 2;                         // j / NP_

    if (lane < P) {
        #pragma unroll
        for (int dy = 0; dy < 2; dy++) {
            int yi = y0 + dy;
            float wy = dy ? wy1 : 1.0f - wy1;
            #pragma unroll
            for (int dx = 0; dx < 2; dx++) {
                int xi = x0 + dx;
                bool valid = ((unsigned)yi < 32u) && ((unsigned)xi < 32u);
                float w = valid ? (dx ? wx1 : 1.0f - wx1) * wy * aw : 0.0f;
                unsigned id = valid ? (unsigned)(l * 1024 + yi * 32 + xi) : 0u;
                swc[h][j][dy * 2 + dx] = make_uint2(__float_as_uint(w), id);
            }
        }
    }
    __syncwarp();

    // ---- branch-free gather loop ----
    float2 acc = make_float2(0.f, 0.f);
    #pragma unroll
    for (int s = 0; s < P; s++) {
        #pragma unroll
        for (int c = 0; c < 4; c++) {
            uint2 wc = swc[h][s][c];
            float w = __uint_as_float(wc.x);
            const uint32_t* vp = (const uint32_t*)(vbase + (size_t)wc.y * D_);
            uint32_t pv = vp[lane];
            float2 v = __bfloat1622float2(*reinterpret_cast<__nv_bfloat162*>(&pv));
            acc.x += v.x * w;
            acc.y += v.y * w;
        }
    }
    uint32_t pv = pack_bf16(acc.x, acc.y);
    ((uint32_t*)(out + (size_t)bq * D_ + h * DH_))[lane] = pv;
}

// ---------------------------------------------------------------------------
// Host launcher
// ---------------------------------------------------------------------------
extern "C" void kernel_launch(void* const* d_in, const int* in_sizes, int n_in,
                              void* d_out, int out_size)
{
    const float* src[4] = {(const float*)d_in[0], (const float*)d_in[1],
                           (const float*)d_in[2], (const float*)d_in[3]};
    const float* qn_g = (const float*)d_in[4];
    const float* qn_b = (const float*)d_in[5];
    const float* fn_g = (const float*)d_in[6];
    const float* fn_b = (const float*)d_in[7];
    const float* n1_g = (const float*)d_in[8];
    const float* n1_b = (const float*)d_in[9];
    const float* gamma1 = (const float*)d_in[10];
    const float* gamma2 = (const float*)d_in[11];
    const float* ca_vb = (const float*)d_in[13];
    const float* ca_ob = (const float*)d_in[15];
    const float* ca_ab = (const float*)d_in[17];
    const float* ca_pb = (const float*)d_in[19];
    const float* sa_vb = (const float*)d_in[21];
    const float* sa_ob = (const float*)d_in[23];
    const float* sa_ab = (const float*)d_in[25];
    const float* sa_pb = (const float*)d_in[27];

    bf16 *fn, *qn, *val, *samp, *attn1, *val2, *samp2, *wr;
    float *offaw, *attn, *offaw2;
    cudaGetSymbolAddress((void**)&fn,     g_fn);
    cudaGetSymbolAddress((void**)&qn,     g_qn);
    cudaGetSymbolAddress((void**)&val,    g_val);
    cudaGetSymbolAddress((void**)&offaw,  g_offaw);
    cudaGetSymbolAddress((void**)&samp,   g_samp);
    cudaGetSymbolAddress((void**)&attn,   g_attn);
    cudaGetSymbolAddress((void**)&attn1,  g_attn1);
    cudaGetSymbolAddress((void**)&val2,   g_val2);
    cudaGetSymbolAddress((void**)&offaw2, g_offaw2);
    cudaGetSymbolAddress((void**)&samp2,  g_samp2);
    cudaGetSymbolAddress((void**)&wr,     g_wrb);

    const int ROWS = B_ * LQ_;                    // 4096
    const int SMEM = 2 * NSTAGE * STGB;           // 81920 bytes

    cudaFuncSetAttribute(gemm_dual, cudaFuncAttributeMaxDynamicSharedMemorySize, SMEM);

    PrepArgs pa = { src[0], src[1], src[2], src[3],
                    fn_g, fn_b, qn_g, qn_b,
                    fn, qn, wr,
                    (const float4*)d_in[12], (const float4*)d_in[14],
                    (const float4*)d_in[16], (const float4*)d_in[18],
                    (const float4*)d_in[20], (const float4*)d_in[22],
                    (const float4*)d_in[24], (const float4*)d_in[26] };

    const float* Z = nullptr;
    // Descriptors {A, W, b1, b2, split, C, N, gx, mode, fs3, fat, fg1, fg2}
    GDesc dCAoffaw = { qn,    wr + WOFF_CAOW, ca_ob, ca_ab, 512,  offaw,  768,  6, 0, Z, Z, Z, Z };
    GDesc dCAval   = { fn,    wr + WOFF_CAVW, ca_vb, ca_vb, 1024, val,    1024, 8, 1, Z, Z, Z, Z };
    GDesc dCAproj  = { samp,  wr + WOFF_CAPW, ca_pb, ca_pb, 1024, attn,   1024, 8, 0, Z, Z, Z, Z };
    GDesc dSAval   = { attn1, wr + WOFF_SAVW, sa_vb, sa_vb, 1024, val2,   1024, 8, 1, Z, Z, Z, Z };
    GDesc dSAoffaw = { attn1, wr + WOFF_SAOW, sa_ob, sa_ab, 128,  offaw2, 192,  2, 0, Z, Z, Z, Z };
    GDesc dSAproj  = { samp2, wr + WOFF_SAPW, sa_pb, sa_pb, 1024, d_out,  1024, 8, 2,
                       src[3], attn, gamma1, gamma2 };

    // 1) Merged prologue: feat-LN || qn-LN || weight conversion
    prep_kernel<<<2560 + (WTOT / 4 + 255) / 256, 256>>>(pa);
    // 2) Combined CA GEMMs: off+aw (192 CTAs) || value (1024 CTAs)
    gemm_dual<<<192 + 1024, 256, SMEM>>>(dCAoffaw, dCAval, 192);
    // 3) CA sampler (fused softmax, smem-staged corner weights)
    deform_sample<4><<<ROWS, 512>>>(val, offaw, 768, 512, samp);
    // 4) CA projection -> attn (fp32 + bias)
    gemm_dual<<<256, 256, SMEM>>>(dCAproj, dCAproj, 256);
    // 5) LN(attn) -> attn1
    ln_kernel<<<ROWS / 8, 256>>>(attn, n1_g, n1_b, attn1);
    // 6) SA value || SA off+aw
    gemm_dual<<<256 + 64, 256, SMEM>>>(dSAval, dSAoffaw, 256);
    // 7) SA sampler
    deform_sample<1><<<ROWS, 512>>>(val2, offaw2, 192, 128, samp2);
    // 8) SA projection with FINAL fused epilogue -> d_out
    gemm_dual<<<256, 256, SMEM>>>(dSAproj, dSAproj, 256);
}

// round 17
// speedup vs baseline: 1.2141x; 1.0092x over previous
#include <cuda_runtime.h>
#include <cuda_bf16.h>
#include <math.h>
#include <stdint.h>

typedef __nv_bfloat16 bf16;

// Problem constants
#define B_   4
#define E_   32
#define D_   1024
#define NH_  16
#define NP_  4
#define LQ_  1024          // E*E
#define DH_  64            // D/NH

// ---------------------------------------------------------------------------
// Scratch (static device globals; allocation APIs are forbidden)
// ---------------------------------------------------------------------------
__device__ bf16  g_fn    [B_ * 4 * LQ_ * D_];   // 32 MB  LN(concat srcs), bf16
__device__ bf16  g_qn    [B_ * LQ_ * D_];       //  8 MB  LN(src3), bf16
__device__ bf16  g_val   [B_ * 4 * LQ_ * D_];   // 32 MB  CA value (bf16)
__device__ float g_offaw [B_ * LQ_ * 768];      // 12 MB  CA off(512)+aw(256, raw logits)
__device__ bf16  g_samp  [B_ * LQ_ * D_];       //  8 MB  CA sampled, bf16
__device__ float g_attn  [B_ * LQ_ * D_];       // 16 MB
__device__ bf16  g_attn1 [B_ * LQ_ * D_];       //  8 MB  LN(attn), bf16
__device__ bf16  g_val2  [B_ * LQ_ * D_];       //  8 MB  SA value (bf16)
__device__ float g_offaw2[B_ * LQ_ * 192];      //  3 MB  SA off(128)+aw(64, raw logits)
__device__ bf16  g_samp2 [B_ * LQ_ * D_];       //  8 MB  bf16
__device__ bf16  g_wrb   [5177344];             // 10.4 MB bf16 weights

// Weight segment offsets (elements) inside g_wrb
#define WOFF_CAVW 0
#define WOFF_CAOW 1048576
#define WOFF_CAAW 1572864
#define WOFF_CAPW 1835008
#define WOFF_SAVW 2883584
#define WOFF_SAOW 3932160
#define WOFF_SAAW 4063232
#define WOFF_SAPW 4128768
#define WTOT      5177344

// ---------------------------------------------------------------------------
// Helpers
// ---------------------------------------------------------------------------
__device__ __forceinline__ uint32_t smem_u32(const void* p) {
    uint32_t a;
    asm("{ .reg .u64 t; cvta.to.shared.u64 t, %1; cvt.u32.u64 %0, t; }"
        : "=r"(a) : "l"(p));
    return a;
}
__device__ __forceinline__ void cp16(uint32_t s, const void* g) {
    asm volatile("cp.async.cg.shared.global [%0], [%1], 16;\n" :: "r"(s), "l"(g));
}
__device__ __forceinline__ void cp16p(uint32_t s, const void* g, uint32_t nbytes) {
    asm volatile("cp.async.cg.shared.global [%0], [%1], 16, %2;\n"
                 :: "r"(s), "l"(g), "r"(nbytes));
}
__device__ __forceinline__ void ldsm4(uint32_t* r, uint32_t a) {
    asm volatile("ldmatrix.sync.aligned.m8n8.x4.shared.b16 {%0,%1,%2,%3}, [%4];"
                 : "=r"(r[0]), "=r"(r[1]), "=r"(r[2]), "=r"(r[3]) : "r"(a));
}
__device__ __forceinline__ void mma_bf16(float* d, const uint32_t* a,
                                         uint32_t b0, uint32_t b1) {
    asm volatile(
        "mma.sync.aligned.m16n8k16.row.col.f32.bf16.bf16.f32 "
        "{%0,%1,%2,%3}, {%4,%5,%6,%7}, {%8,%9}, {%0,%1,%2,%3};"
        : "+f"(d[0]), "+f"(d[1]), "+f"(d[2]), "+f"(d[3])
        : "r"(a[0]), "r"(a[1]), "r"(a[2]), "r"(a[3]), "r"(b0), "r"(b1));
}
__device__ __forceinline__ uint32_t pack_bf16(float lo, float hi) {
    __nv_bfloat162 p = __floats2bfloat162_rn(lo, hi);
    return *reinterpret_cast<uint32_t*>(&p);
}

// ---------------------------------------------------------------------------
// BF16 tensor-core GEMM body (at legacy-HMMA issue floor per SM; BN=128).
// Block 128x128x32, 256 threads / 8 warps (warp 32x64), 4-stage cp.async,
// wait_group 2. gemm_dual packs two independent descriptors in ONE launch.
// mode: 0 = fp32 C + bias, 1 = bf16 C + bias,
//       2 = FINAL: C(out) = fs3 + g1*(fat + g2*(acc + bias))   [fp32, N=1024]
// ---------------------------------------------------------------------------
#define RSTR 80              // bytes per smem row
#define STGB (128 * RSTR)    // bytes per matrix per stage (10240)
#define NSTAGE 4

struct GDesc {
    const bf16* A; const bf16* W;
    const float* b1; const float* b2;
    int split; void* C; int N; int gx; int mode;
    const float* fs3; const float* fat; const float* fg1; const float* fg2;
};

__device__ __forceinline__ void gemm_body(const GDesc d, int bx, int by)
{
    extern __shared__ char smraw[];
    uint32_t abase = smem_u32(smraw);
    uint32_t bbase = abase + NSTAGE * STGB;

    const int K = 1024, NIT = 32;
    int tid = threadIdx.x, wid = tid >> 5, lane = tid & 31;
    int wm = wid & 3, wn = wid >> 2;
    int bm = by * 128, bn = bx * 128;
    int N = d.N;

    float acc[2][8][4];
    #pragma unroll
    for (int mt = 0; mt < 2; mt++)
        #pragma unroll
        for (int nt = 0; nt < 8; nt++)
            #pragma unroll
            for (int i = 0; i < 4; i++) acc[mt][nt][i] = 0.f;

    int rowC = tid >> 2, jc = tid & 3;

    auto load_stage = [&](int s, int it) {
        int k0 = it * 32;
        #pragma unroll
        for (int i = 0; i < 2; ++i) {
            int row = rowC + i * 64;
            cp16(abase + s * STGB + row * RSTR + jc * 16,
                 d.A + (size_t)(bm + row) * K + k0 + jc * 8);
            int srow = bn + row;
            const bf16* src = d.W + (size_t)(srow < N ? srow : 0) * K + k0 + jc * 8;
            cp16p(bbase + s * STGB + row * RSTR + jc * 16,
                  src, srow < N ? 16u : 0u);
        }
        asm volatile("cp.async.commit_group;" ::: "memory");
    };

    int rA = lane & 15, hA = lane >> 4;
    uint32_t aAddr = abase + (uint32_t)(wm * 32 + rA) * RSTR + hA * 16;
    int rB = (lane & 7) | ((lane >> 4) << 3);
    int hB = (lane >> 3) & 1;
    uint32_t bAddr = bbase + (uint32_t)(wn * 64 + rB) * RSTR + hB * 16;

    load_stage(0, 0);
    load_stage(1, 1);
    load_stage(2, 2);

    int s = 0, pf = 3;
    for (int it = 0; it < NIT; ++it) {
        asm volatile("cp.async.wait_group 2;" ::: "memory");
        __syncthreads();
        if (it + 3 < NIT) {
            load_stage(pf, it + 3);
            pf = (pf == NSTAGE - 1) ? 0 : pf + 1;
        }

        uint32_t ao = aAddr + s * STGB;
        uint32_t bo = bAddr + s * STGB;
        #pragma unroll
        for (int ks = 0; ks < 2; ks++) {
            uint32_t af[2][4];
            #pragma unroll
            for (int mt = 0; mt < 2; mt++)
                ldsm4(af[mt], ao + mt * (16 * RSTR) + ks * 32);
            #pragma unroll
            for (int nb = 0; nb < 4; nb++) {
                uint32_t bb4[4];
                ldsm4(bb4, bo + nb * (16 * RSTR) + ks * 32);
                #pragma unroll
                for (int mt = 0; mt < 2; mt++) {
                    mma_bf16(acc[mt][2 * nb],     af[mt], bb4[0], bb4[1]);
                    mma_bf16(acc[mt][2 * nb + 1], af[mt], bb4[2], bb4[3]);
                }
            }
        }
        s = (s == NSTAGE - 1) ? 0 : s + 1;
    }

    // Epilogue (split-bias; mode-selected output transform)
    int gq = lane >> 2, c = lane & 3;
    #pragma unroll
    for (int mt = 0; mt < 2; mt++) {
        int r0 = bm + wm * 32 + mt * 16 + gq;
        #pragma unroll
        for (int nt = 0; nt < 8; nt++) {
            int colb = bn + wn * 64 + nt * 8;
            if (colb < N) {
                int cg = colb + 2 * c;
                const float* bp = (colb < d.split) ? (d.b1 + cg) : (d.b2 + cg - d.split);
                float2 bv = *(const float2*)bp;
                float v00 = acc[mt][nt][0] + bv.x, v01 = acc[mt][nt][1] + bv.y;
                float v10 = acc[mt][nt][2] + bv.x, v11 = acc[mt][nt][3] + bv.y;
                if (d.mode == 1) {
                    *(uint32_t*)((bf16*)d.C + (size_t)r0 * N + cg) = pack_bf16(v00, v01);
                    *(uint32_t*)((bf16*)d.C + (size_t)(r0 + 8) * N + cg) = pack_bf16(v10, v11);
                } else if (d.mode == 0) {
                    *(float2*)((float*)d.C + (size_t)r0 * N + cg) = make_float2(v00, v01);
                    *(float2*)((float*)d.C + (size_t)(r0 + 8) * N + cg) = make_float2(v10, v11);
                } else {
                    float2 G1 = *(const float2*)(d.fg1 + cg);
                    float2 G2 = *(const float2*)(d.fg2 + cg);
                    float2 s0v = *(const float2*)(d.fs3 + (size_t)r0 * N + cg);
                    float2 a0v = *(const float2*)(d.fat + (size_t)r0 * N + cg);
                    float2 o0 = { s0v.x + G1.x * (a0v.x + G2.x * v00),
                                  s0v.y + G1.y * (a0v.y + G2.y * v01) };
                    *(float2*)((float*)d.C + (size_t)r0 * N + cg) = o0;
                    float2 s1v = *(const float2*)(d.fs3 + (size_t)(r0 + 8) * N + cg);
                    float2 a1v = *(const float2*)(d.fat + (size_t)(r0 + 8) * N + cg);
                    float2 o1 = { s1v.x + G1.x * (a1v.x + G2.x * v10),
                                  s1v.y + G1.y * (a1v.y + G2.y * v11) };
                    *(float2*)((float*)d.C + (size_t)(r0 + 8) * N + cg) = o1;
                }
            }
        }
    }
}

__global__ void __launch_bounds__(256, 2) gemm_dual(GDesc d0, GDesc d1, int n0)
{
    int cta = blockIdx.x;
    if (cta < n0) {
        gemm_body(d0, cta % d0.gx, cta / d0.gx);
    } else {
        int idx = cta - n0;
        gemm_body(d1, idx % d1.gx, idx / d1.gx);
    }
}

// ---------------------------------------------------------------------------
// Warp-per-row LN body (pure shfl reduction). fp32 row -> bf16 row(s).
// Optional second output with different gamma/beta reusing the normalization
// (used to produce qn from the same src3 pass as the feat-LN l==3 rows).
// ---------------------------------------------------------------------------
__device__ __forceinline__ void ln_row2(
    const float4* __restrict__ x4, const float* __restrict__ g,
    const float* __restrict__ b, uint2* __restrict__ orow,
    const float* __restrict__ g2, const float* __restrict__ b2,
    uint2* __restrict__ orow2, int lane)
{
    float4 v[8];
    float s = 0.f, ss = 0.f;
    #pragma unroll
    for (int i = 0; i < 8; i++) {
        v[i] = x4[lane + 32 * i];
        s  += v[i].x + v[i].y + v[i].z + v[i].w;
        ss += v[i].x * v[i].x + v[i].y * v[i].y + v[i].z * v[i].z + v[i].w * v[i].w;
    }
    #pragma unroll
    for (int o = 16; o; o >>= 1) {
        s  += __shfl_xor_sync(0xFFFFFFFFu, s,  o);
        ss += __shfl_xor_sync(0xFFFFFFFFu, ss, o);
    }
    float mean = s * (1.0f / D_);
    float var  = ss * (1.0f / D_) - mean * mean;
    float inv  = rsqrtf(var + 1e-6f);

    #pragma unroll
    for (int i = 0; i < 8; i++) {
        float nx = (v[i].x - mean) * inv, ny = (v[i].y - mean) * inv;
        float nz = (v[i].z - mean) * inv, nw = (v[i].w - mean) * inv;
        float4 gg = ((const float4*)g)[lane + 32 * i];
        float4 bb = ((const float4*)b)[lane + 32 * i];
        uint2 u;
        u.x = pack_bf16(nx * gg.x + bb.x, ny * gg.y + bb.y);
        u.y = pack_bf16(nz * gg.z + bb.z, nw * gg.w + bb.w);
        orow[lane + 32 * i] = u;
        if (orow2) {
            float4 g2v = ((const float4*)g2)[lane + 32 * i];
            float4 b2v = ((const float4*)b2)[lane + 32 * i];
            uint2 u2;
            u2.x = pack_bf16(nx * g2v.x + b2v.x, ny * g2v.y + b2v.y);
            u2.y = pack_bf16(nz * g2v.z + b2v.z, nw * g2v.w + b2v.w);
            orow2[lane + 32 * i] = u2;
        }
    }
}

__global__ void __launch_bounds__(256) ln_kernel(
    const float* __restrict__ in, const float* __restrict__ g,
    const float* __restrict__ b, bf16* __restrict__ out)
{
    int w = threadIdx.x >> 5, lane = threadIdx.x & 31;
    int r = blockIdx.x * 8 + w;
    ln_row2((const float4*)(in + (size_t)r * D_), g, b,
            (uint2*)(out + (size_t)r * D_), nullptr, nullptr, nullptr, lane);
}

// ---------------------------------------------------------------------------
// Merged prologue: blocks [0,2048) feat-LN (l==3 rows also emit qn via the
// shared normalization), [2048, 2048+5056) weight bf16 conversion.
// ---------------------------------------------------------------------------
struct PrepArgs {
    const float *s0, *s1, *s2, *s3;
    const float *fng, *fnb, *qng, *qnb;
    bf16 *fn, *qn, *wrb;
    const float4 *w0, *w1, *w2, *w3, *w4, *w5, *w6, *w7;
};

__global__ void __launch_bounds__(256) prep_kernel(PrepArgs a)
{
    int bid = blockIdx.x, tid = threadIdx.x;
    if (bid < 2048) {
        int w = tid >> 5, lane = tid & 31;
        int row = bid * 8 + w;             // 0..16383
        int l = row >> 12, r = row & 4095;
        const float* in = (l == 0) ? a.s0 : (l == 1) ? a.s1 : (l == 2) ? a.s2 : a.s3;
        int bb = r >> 10, rr = r & 1023;
        uint2* qrow = (l == 3) ? (uint2*)(a.qn + (size_t)r * D_) : nullptr;
        ln_row2((const float4*)(in + (size_t)r * D_), a.fng, a.fnb,
                (uint2*)(a.fn + ((size_t)bb * 4096 + l * 1024 + rr) * D_),
                a.qng, a.qnb, qrow, lane);
    } else {
        int i = (bid - 2048) * 256 + tid;      // float4 index
        if (i >= WTOT / 4) return;
        const float4* src; int base;
        if      (i < WOFF_CAOW/4) { src = a.w0; base = 0; }
        else if (i < WOFF_CAAW/4) { src = a.w1; base = WOFF_CAOW/4; }
        else if (i < WOFF_CAPW/4) { src = a.w2; base = WOFF_CAAW/4; }
        else if (i < WOFF_SAVW/4) { src = a.w3; base = WOFF_CAPW/4; }
        else if (i < WOFF_SAOW/4) { src = a.w4; base = WOFF_SAVW/4; }
        else if (i < WOFF_SAAW/4) { src = a.w5; base = WOFF_SAOW/4; }
        else if (i < WOFF_SAPW/4) { src = a.w6; base = WOFF_SAAW/4; }
        else                      { src = a.w7; base = WOFF_SAPW/4; }
        float4 v = src[i - base];
        uint2 u;
        u.x = pack_bf16(v.x, v.y);
        u.y = pack_bf16(v.z, v.w);
        ((uint2*)a.wrb)[i] = u;
    }
}

// ---------------------------------------------------------------------------
// Deformable sampling, de-redundified (round-16 structure) with bit-op bf16
// unpack (<<16 / &0xFFFF0000, exact) and dual accumulators to shorten the
// FFMA dependency chain. 1 block per (b,q), 16 warps = heads.
// ---------------------------------------------------------------------------
template<int NL>
__global__ void __launch_bounds__(512) deform_sample(
    const bf16* __restrict__ value, const float* __restrict__ comb,
    int rstride, int aoff, bf16* __restrict__ out)
{
    constexpr int P = NL * NP_;
    __shared__ uint2 swc[16][P][4];

    int bq = blockIdx.x;
    int b = bq >> 10, q = bq & 1023;
    int h = threadIdx.x >> 5, lane = threadIdx.x & 31;

    const bf16* vbase = value + (size_t)b * (NL * 1024) * D_ + h * DH_;

    // ---- per-sample setup on lanes (duplicated mod P) ----
    int j = lane & (P - 1);
    const float* base = comb + (size_t)bq * rstride;
    float ox    = base[h * (P * 2) + 2 * j];
    float oy    = base[h * (P * 2) + 2 * j + 1];
    float logit = base[aoff + h * P + j];

    float m = logit;
    #pragma unroll
    for (int o = P / 2; o; o >>= 1)
        m = fmaxf(m, __shfl_xor_sync(0xFFFFFFFFu, m, o, P));
    float e = __expf(logit - m);
    float sum = e;
    #pragma unroll
    for (int o = P / 2; o; o >>= 1)
        sum += __shfl_xor_sync(0xFFFFFFFFu, sum, o, P);
    float aw = e / sum;

    float rx = ((q & 31) + 0.5f) * 0.03125f;
    float ry = ((q >> 5) + 0.5f) * 0.03125f;
    float x = (rx + ox * 0.03125f) * 32.0f - 0.5f;
    float y = (ry + oy * 0.03125f) * 32.0f - 0.5f;
    float x0f = floorf(x), y0f = floorf(y);
    float wx1 = x - x0f, wy1 = y - y0f;
    int x0 = (int)x0f, y0 = (int)y0f;
    int l = j >> 2;                         // j / NP_

    if (lane < P) {
        #pragma unroll
        for (int dy = 0; dy < 2; dy++) {
            int yi = y0 + dy;
            float wy = dy ? wy1 : 1.0f - wy1;
            #pragma unroll
            for (int dx = 0; dx < 2; dx++) {
                int xi = x0 + dx;
                bool valid = ((unsigned)yi < 32u) && ((unsigned)xi < 32u);
                float w = valid ? (dx ? wx1 : 1.0f - wx1) * wy * aw : 0.0f;
                unsigned id = valid ? (unsigned)(l * 1024 + yi * 32 + xi) : 0u;
                swc[h][j][dy * 2 + dx] = make_uint2(__float_as_uint(w), id);
            }
        }
    }
    __syncwarp();

    // ---- branch-free gather loop, two accumulators ----
    float2 acc0 = make_float2(0.f, 0.f), acc1 = make_float2(0.f, 0.f);
    #pragma unroll
    for (int s = 0; s < P; s++) {
        #pragma unroll
        for (int c = 0; c < 4; c += 2) {
            uint2 wc0 = swc[h][s][c];
            uint2 wc1 = swc[h][s][c + 1];
            uint32_t pv0 = ((const uint32_t*)(vbase + (size_t)wc0.y * D_))[lane];
            uint32_t pv1 = ((const uint32_t*)(vbase + (size_t)wc1.y * D_))[lane];
            float w0 = __uint_as_float(wc0.x);
            float w1 = __uint_as_float(wc1.x);
            acc0.x += __uint_as_float(pv0 << 16) * w0;
            acc0.y += __uint_as_float(pv0 & 0xFFFF0000u) * w0;
            acc1.x += __uint_as_float(pv1 << 16) * w1;
            acc1.y += __uint_as_float(pv1 & 0xFFFF0000u) * w1;
        }
    }
    uint32_t pv = pack_bf16(acc0.x + acc1.x, acc0.y + acc1.y);
    ((uint32_t*)(out + (size_t)bq * D_ + h * DH_))[lane] = pv;
}

// ---------------------------------------------------------------------------
// Host launcher
// ---------------------------------------------------------------------------
extern "C" void kernel_launch(void* const* d_in, const int* in_sizes, int n_in,
                              void* d_out, int out_size)
{
    const float* src[4] = {(const float*)d_in[0], (const float*)d_in[1],
                           (const float*)d_in[2], (const float*)d_in[3]};
    const float* qn_g = (const float*)d_in[4];
    const float* qn_b = (const float*)d_in[5];
    const float* fn_g = (const float*)d_in[6];
    const float* fn_b = (const float*)d_in[7];
    const float* n1_g = (const float*)d_in[8];
    const float* n1_b = (const float*)d_in[9];
    const float* gamma1 = (const float*)d_in[10];
    const float* gamma2 = (const float*)d_in[11];
    const float* ca_vb = (const float*)d_in[13];
    const float* ca_ob = (const float*)d_in[15];
    const float* ca_ab = (const float*)d_in[17];
    const float* ca_pb = (const float*)d_in[19];
    const float* sa_vb = (const float*)d_in[21];
    const float* sa_ob = (const float*)d_in[23];
    const float* sa_ab = (const float*)d_in[25];
    const float* sa_pb = (const float*)d_in[27];

    bf16 *fn, *qn, *val, *samp, *attn1, *val2, *samp2, *wr;
    float *offaw, *attn, *offaw2;
    cudaGetSymbolAddress((void**)&fn,     g_fn);
    cudaGetSymbolAddress((void**)&qn,     g_qn);
    cudaGetSymbolAddress((void**)&val,    g_val);
    cudaGetSymbolAddress((void**)&offaw,  g_offaw);
    cudaGetSymbolAddress((void**)&samp,   g_samp);
    cudaGetSymbolAddress((void**)&attn,   g_attn);
    cudaGetSymbolAddress((void**)&attn1,  g_attn1);
    cudaGetSymbolAddress((void**)&val2,   g_val2);
    cudaGetSymbolAddress((void**)&offaw2, g_offaw2);
    cudaGetSymbolAddress((void**)&samp2,  g_samp2);
    cudaGetSymbolAddress((void**)&wr,     g_wrb);

    const int ROWS = B_ * LQ_;                    // 4096
    const int SMEM = 2 * NSTAGE * STGB;           // 81920 bytes

    cudaFuncSetAttribute(gemm_dual, cudaFuncAttributeMaxDynamicSharedMemorySize, SMEM);

    PrepArgs pa = { src[0], src[1], src[2], src[3],
                    fn_g, fn_b, qn_g, qn_b,
                    fn, qn, wr,
                    (const float4*)d_in[12], (const float4*)d_in[14],
                    (const float4*)d_in[16], (const float4*)d_in[18],
                    (const float4*)d_in[20], (const float4*)d_in[22],
                    (const float4*)d_in[24], (const float4*)d_in[26] };

    const float* Z = nullptr;
    // Descriptors {A, W, b1, b2, split, C, N, gx, mode, fs3, fat, fg1, fg2}
    GDesc dCAoffaw = { qn,    wr + WOFF_CAOW, ca_ob, ca_ab, 512,  offaw,  768,  6, 0, Z, Z, Z, Z };
    GDesc dCAval   = { fn,    wr + WOFF_CAVW, ca_vb, ca_vb, 1024, val,    1024, 8, 1, Z, Z, Z, Z };
    GDesc dCAproj  = { samp,  wr + WOFF_CAPW, ca_pb, ca_pb, 1024, attn,   1024, 8, 0, Z, Z, Z, Z };
    GDesc dSAval   = { attn1, wr + WOFF_SAVW, sa_vb, sa_vb, 1024, val2,   1024, 8, 1, Z, Z, Z, Z };
    GDesc dSAoffaw = { attn1, wr + WOFF_SAOW, sa_ob, sa_ab, 128,  offaw2, 192,  2, 0, Z, Z, Z, Z };
    GDesc dSAproj  = { samp2, wr + WOFF_SAPW, sa_pb, sa_pb, 1024, d_out,  1024, 8, 2,
                       src[3], attn, gamma1, gamma2 };

    // 1) Merged prologue: feat-LN (incl. qn via shared normalization) || weights
    prep_kernel<<<2048 + (WTOT / 4 + 255) / 256, 256>>>(pa);
    // 2) Combined CA GEMMs: off+aw (192 CTAs) || value (1024 CTAs)
    gemm_dual<<<192 + 1024, 256, SMEM>>>(dCAoffaw, dCAval, 192);
    // 3) CA sampler (fused softmax, smem-staged corner weights)
    deform_sample<4><<<ROWS, 512>>>(val, offaw, 768, 512, samp);
    // 4) CA projection -> attn (fp32 + bias)
    gemm_dual<<<256, 256, SMEM>>>(dCAproj, dCAproj, 256);
    // 5) LN(attn) -> attn1
    ln_kernel<<<ROWS / 8, 256>>>(attn, n1_g, n1_b, attn1);
    // 6) SA value || SA off+aw
    gemm_dual<<<256 + 64, 256, SMEM>>>(dSAval, dSAoffaw, 256);
    // 7) SA sampler
    deform_sample<1><<<ROWS, 512>>>(val2, offaw2, 192, 128, samp2);
    // 8) SA projection with FINAL fused epilogue -> d_out
    gemm_dual<<<256, 256, SMEM>>>(dSAproj, dSAproj, 256);
}